// round 2
// baseline (speedup 1.0000x reference)
#include <cuda_runtime.h>
#include <math.h>

#define NTOK   4096
#define DMODEL 1024
#define DINTER 704
#define NEXP   16

#define BM 64
#define BN 64
#define BK 16
#define XPAD 4

// ---- device scratch (no allocations allowed) ----
__device__ int   g_cnt[NEXP];
__device__ int   g_slot[NEXP][NTOK];   // token*2 + rank-in-top2
__device__ float g_gate[NEXP][NTOK];
__device__ float g_H[(size_t)NTOK * 2 * DINTER];   // 23 MB intermediate h rows

// ---------------------------------------------------------------------------
__global__ void k_reset() {
    if (threadIdx.x < NEXP) g_cnt[threadIdx.x] = 0;
}

// one block per token, 128 threads: 16 experts x 8 lanes
__global__ void k_router(const float* __restrict__ x, const float* __restrict__ Wg) {
    int n = blockIdx.x;
    const float* xr = x + (size_t)n * DMODEL;
    int tid = threadIdx.x;
    int e = tid >> 3, l = tid & 7;
    const float* wr = Wg + e * DMODEL;
    float s = 0.f;
#pragma unroll 8
    for (int d = l; d < DMODEL; d += 8) s += xr[d] * wr[d];
    s += __shfl_down_sync(0xffffffffu, s, 4);
    s += __shfl_down_sync(0xffffffffu, s, 2);
    s += __shfl_down_sync(0xffffffffu, s, 1);
    __shared__ float logits[NEXP];
    if (l == 0) logits[e] = s;
    __syncthreads();
    if (tid == 0) {
        int i1 = 0; float v1 = logits[0];
#pragma unroll
        for (int j = 1; j < NEXP; j++) if (logits[j] > v1) { v1 = logits[j]; i1 = j; }
        int i2 = -1; float v2 = -3.4e38f;
#pragma unroll
        for (int j = 0; j < NEXP; j++) if (j != i1 && logits[j] > v2) { v2 = logits[j]; i2 = j; }
        // softmax + top2 + renorm == e^{l1}/(e^{l1}+e^{l2}) for top-2 logits
        float w1 = 1.f / (1.f + expf(v2 - v1));
        float w2 = 1.f - w1;
        int p1 = atomicAdd(&g_cnt[i1], 1);
        g_slot[i1][p1] = n * 2;     g_gate[i1][p1] = w1;
        int p2 = atomicAdd(&g_cnt[i2], 1);
        g_slot[i2][p2] = n * 2 + 1; g_gate[i2][p2] = w2;
    }
}

// ---------------------------------------------------------------------------
// GEMM1: per expert, gathered rows of x:  h = silu(x W1) * (x W3) -> g_H
// grid: (NTOK/BM, DINTER/BN, NEXP), 256 threads, 4x4 register tile, dual accum
__global__ __launch_bounds__(256)
void k_gemm1(const float* __restrict__ x,
             const float* __restrict__ W1g,
             const float* __restrict__ W3g) {
    int e = blockIdx.z;
    int cnt = g_cnt[e];
    int m0 = blockIdx.x * BM;
    if (m0 >= cnt) return;
    int n0 = blockIdx.y * BN;
    const float* w1 = W1g + (size_t)e * DMODEL * DINTER;
    const float* w3 = W3g + (size_t)e * DMODEL * DINTER;

    __shared__ float Xs[BK][BM + XPAD];
    __shared__ float W1s[BK][BN];
    __shared__ float W3s[BK][BN];
    __shared__ int   hrow[BM];

    int tid = threadIdx.x;
    if (tid < BM) {
        int m = m0 + tid;
        int slot = g_slot[e][(m < cnt) ? m : (cnt - 1)];
        hrow[tid] = slot;
    }
    __syncthreads();

    int tx = tid & 15;   // n dir
    int ty = tid >> 4;   // m dir
    float acc1[4][4], acc3[4][4];
#pragma unroll
    for (int i = 0; i < 4; i++)
#pragma unroll
        for (int j = 0; j < 4; j++) { acc1[i][j] = 0.f; acc3[i][j] = 0.f; }

    int lm   = tid >> 2;           // 0..63  (gathered row)
    int lseg = (tid & 3) << 2;     // 0,4,8,12 (k offset)
    const float* xrow = x + (size_t)(hrow[lm] >> 1) * DMODEL;

    int wk = tid >> 4;             // 0..15
    int wn = (tid & 15) << 2;      // 0..60

    for (int k0 = 0; k0 < DMODEL; k0 += BK) {
        float4 xv  = *(const float4*)(xrow + k0 + lseg);
        float4 w1v = *(const float4*)(w1 + (size_t)(k0 + wk) * DINTER + n0 + wn);
        float4 w3v = *(const float4*)(w3 + (size_t)(k0 + wk) * DINTER + n0 + wn);
        __syncthreads();
        Xs[lseg + 0][lm] = xv.x;
        Xs[lseg + 1][lm] = xv.y;
        Xs[lseg + 2][lm] = xv.z;
        Xs[lseg + 3][lm] = xv.w;
        *(float4*)&W1s[wk][wn] = w1v;
        *(float4*)&W3s[wk][wn] = w3v;
        __syncthreads();
#pragma unroll
        for (int kk = 0; kk < BK; kk++) {
            float4 a  = *(const float4*)&Xs[kk][ty * 4];
            float4 b1 = *(const float4*)&W1s[kk][tx * 4];
            float4 b3 = *(const float4*)&W3s[kk][tx * 4];
            float av[4]  = {a.x, a.y, a.z, a.w};
            float b1v[4] = {b1.x, b1.y, b1.z, b1.w};
            float b3v[4] = {b3.x, b3.y, b3.z, b3.w};
#pragma unroll
            for (int i = 0; i < 4; i++)
#pragma unroll
                for (int j = 0; j < 4; j++) {
                    acc1[i][j] += av[i] * b1v[j];
                    acc3[i][j] += av[i] * b3v[j];
                }
        }
    }

#pragma unroll
    for (int i = 0; i < 4; i++) {
        int m = ty * 4 + i;
        if (m0 + m < cnt) {
            float* hout = g_H + (size_t)hrow[m] * DINTER + n0;
#pragma unroll
            for (int j = 0; j < 4; j++) {
                float a = acc1[i][j];
                float hval = (a / (1.f + expf(-a))) * acc3[i][j];
                hout[tx * 4 + j] = hval;
            }
        }
    }
}

// ---------------------------------------------------------------------------
// GEMM2: out[token] += gate * (h @ W2),  atomicAdd combine (exactly 2 adds/elem)
// grid: (NTOK/BM, DMODEL/BN, NEXP)
__global__ __launch_bounds__(256)
void k_gemm2(const float* __restrict__ W2g, float* __restrict__ out) {
    int e = blockIdx.z;
    int cnt = g_cnt[e];
    int m0 = blockIdx.x * BM;
    if (m0 >= cnt) return;
    int n0 = blockIdx.y * BN;
    const float* w2 = W2g + (size_t)e * DINTER * DMODEL;

    __shared__ float Hs[BK][BM + XPAD];
    __shared__ float W2s[BK][BN];
    __shared__ int   srow[BM];
    __shared__ float gate[BM];

    int tid = threadIdx.x;
    if (tid < BM) {
        int m = m0 + tid;
        int mm = (m < cnt) ? m : (cnt - 1);
        srow[tid] = g_slot[e][mm];
        gate[tid] = g_gate[e][mm];
    }
    __syncthreads();

    int tx = tid & 15;
    int ty = tid >> 4;
    float acc[4][4];
#pragma unroll
    for (int i = 0; i < 4; i++)
#pragma unroll
        for (int j = 0; j < 4; j++) acc[i][j] = 0.f;

    int lm   = tid >> 2;
    int lseg = (tid & 3) << 2;
    const float* hrowp = g_H + (size_t)srow[lm] * DINTER;
    int wk = tid >> 4;
    int wn = (tid & 15) << 2;

    for (int k0 = 0; k0 < DINTER; k0 += BK) {   // 44 iterations
        float4 hv  = *(const float4*)(hrowp + k0 + lseg);
        float4 w2v = *(const float4*)(w2 + (size_t)(k0 + wk) * DMODEL + n0 + wn);
        __syncthreads();
        Hs[lseg + 0][lm] = hv.x;
        Hs[lseg + 1][lm] = hv.y;
        Hs[lseg + 2][lm] = hv.z;
        Hs[lseg + 3][lm] = hv.w;
        *(float4*)&W2s[wk][wn] = w2v;
        __syncthreads();
#pragma unroll
        for (int kk = 0; kk < BK; kk++) {
            float4 a = *(const float4*)&Hs[kk][ty * 4];
            float4 b = *(const float4*)&W2s[kk][tx * 4];
            float av[4] = {a.x, a.y, a.z, a.w};
            float bv[4] = {b.x, b.y, b.z, b.w};
#pragma unroll
            for (int i = 0; i < 4; i++)
#pragma unroll
                for (int j = 0; j < 4; j++)
                    acc[i][j] += av[i] * bv[j];
        }
    }

#pragma unroll
    for (int i = 0; i < 4; i++) {
        int m = ty * 4 + i;
        if (m0 + m < cnt) {
            int tok = srow[m] >> 1;
            float g = gate[m];
            float* op = out + (size_t)tok * DMODEL + n0;
#pragma unroll
            for (int j = 0; j < 4; j++)
                atomicAdd(&op[tx * 4 + j], g * acc[i][j]);
        }
    }
}

// ---------------------------------------------------------------------------
extern "C" void kernel_launch(void* const* d_in, const int* in_sizes, int n_in,
                              void* d_out, int out_size) {
    const float* x  = (const float*)d_in[0];
    const float* Wg = (const float*)d_in[1];
    const float* W1 = (const float*)d_in[2];
    const float* W2 = (const float*)d_in[3];
    const float* W3 = (const float*)d_in[4];
    float* out = (float*)d_out;

    cudaMemsetAsync(d_out, 0, (size_t)out_size * sizeof(float), 0);
    k_reset<<<1, 32>>>();
    k_router<<<NTOK, 128>>>(x, Wg);

    dim3 g1(NTOK / BM, DINTER / BN, NEXP);
    k_gemm1<<<g1, 256>>>(x, W1, W3);

    dim3 g2(NTOK / BM, DMODEL / BN, NEXP);
    k_gemm2<<<g2, 256>>>(W2, out);
}

// round 6
// speedup vs baseline: 2.1923x; 2.1923x over previous
#include <cuda_runtime.h>
#include <cuda_bf16.h>
#include <math.h>
#include <stdint.h>

#define NTOK   4096
#define DMODEL 1024
#define DINTER 704
#define NEXP   16
#define NSLOT  (NTOK*2)

// ---------------- device scratch (no allocations allowed) -------------------
__device__ int   g_cnt[NEXP];
__device__ int   g_slot[NEXP][NTOK];
__device__ float g_gate[NEXP][NTOK];

__device__ __align__(16) __nv_bfloat16 g_xhi[(size_t)NTOK*DMODEL];
__device__ __align__(16) __nv_bfloat16 g_xlo[(size_t)NTOK*DMODEL];
// weights transposed to K-major: W1T/W3T [e][n=704][k=1024], W2T [e][n=1024][k=704]
__device__ __align__(16) __nv_bfloat16 g_w1hi[(size_t)NEXP*DINTER*DMODEL];
__device__ __align__(16) __nv_bfloat16 g_w1lo[(size_t)NEXP*DINTER*DMODEL];
__device__ __align__(16) __nv_bfloat16 g_w3hi[(size_t)NEXP*DINTER*DMODEL];
__device__ __align__(16) __nv_bfloat16 g_w3lo[(size_t)NEXP*DINTER*DMODEL];
__device__ __align__(16) __nv_bfloat16 g_w2hi[(size_t)NEXP*DMODEL*DINTER];
__device__ __align__(16) __nv_bfloat16 g_w2lo[(size_t)NEXP*DMODEL*DINTER];
__device__ __align__(16) __nv_bfloat16 g_hhi[(size_t)NSLOT*DINTER];
__device__ __align__(16) __nv_bfloat16 g_hlo[(size_t)NSLOT*DINTER];

// ---------------- PTX helpers ----------------------------------------------
__device__ __forceinline__ uint32_t s2u(const void* p) {
    uint32_t a;
    asm("{ .reg .u64 t; cvta.to.shared.u64 t, %1; cvt.u32.u64 %0, t; }" : "=r"(a) : "l"(p));
    return a;
}
#define SWZ(o) ((o) ^ (((o) >> 3) & 0x70))

__device__ __forceinline__ void cp16(uint32_t dst, const void* src) {
    asm volatile("cp.async.cg.shared.global [%0], [%1], 16;" :: "r"(dst), "l"(src));
}
#define CP_COMMIT() asm volatile("cp.async.commit_group;" ::: "memory")
#define CP_WAIT1()  asm volatile("cp.async.wait_group 1;" ::: "memory")
#define CP_WAIT0()  asm volatile("cp.async.wait_group 0;" ::: "memory")

__device__ __forceinline__ void ldsm4(uint32_t& r0, uint32_t& r1, uint32_t& r2, uint32_t& r3,
                                      uint32_t addr) {
    asm volatile("ldmatrix.sync.aligned.m8n8.x4.shared.b16 {%0,%1,%2,%3}, [%4];"
                 : "=r"(r0), "=r"(r1), "=r"(r2), "=r"(r3) : "r"(addr));
}
__device__ __forceinline__ void ldsm2(uint32_t& r0, uint32_t& r1, uint32_t addr) {
    asm volatile("ldmatrix.sync.aligned.m8n8.x2.shared.b16 {%0,%1}, [%2];"
                 : "=r"(r0), "=r"(r1) : "r"(addr));
}
__device__ __forceinline__ void mma16816(float* d, const uint32_t* a, const uint32_t* b) {
    asm volatile(
        "mma.sync.aligned.m16n8k16.row.col.f32.bf16.bf16.f32 "
        "{%0,%1,%2,%3},{%4,%5,%6,%7},{%8,%9},{%0,%1,%2,%3};"
        : "+f"(d[0]), "+f"(d[1]), "+f"(d[2]), "+f"(d[3])
        : "r"(a[0]), "r"(a[1]), "r"(a[2]), "r"(a[3]), "r"(b[0]), "r"(b[1]));
}

// ---------------- small kernels ----------------------------------------------
__global__ void k_reset() {
    if (threadIdx.x < NEXP) g_cnt[threadIdx.x] = 0;
}

__global__ void k_router(const float* __restrict__ x, const float* __restrict__ Wg) {
    int n = blockIdx.x;
    const float* xr = x + (size_t)n * DMODEL;
    int tid = threadIdx.x;
    int e = tid >> 3, l = tid & 7;
    const float* wr = Wg + e * DMODEL;
    float s = 0.f;
#pragma unroll 8
    for (int d = l; d < DMODEL; d += 8) s += xr[d] * wr[d];
    s += __shfl_down_sync(0xffffffffu, s, 4);
    s += __shfl_down_sync(0xffffffffu, s, 2);
    s += __shfl_down_sync(0xffffffffu, s, 1);
    __shared__ float logits[NEXP];
    if (l == 0) logits[e] = s;
    __syncthreads();
    if (tid == 0) {
        int i1 = 0; float v1 = logits[0];
#pragma unroll
        for (int j = 1; j < NEXP; j++) if (logits[j] > v1) { v1 = logits[j]; i1 = j; }
        int i2 = -1; float v2 = -3.4e38f;
#pragma unroll
        for (int j = 0; j < NEXP; j++) if (j != i1 && logits[j] > v2) { v2 = logits[j]; i2 = j; }
        float w1 = 1.f / (1.f + expf(v2 - v1));
        float w2 = 1.f - w1;
        int p1 = atomicAdd(&g_cnt[i1], 1);
        g_slot[i1][p1] = n * 2;     g_gate[i1][p1] = w1;
        int p2 = atomicAdd(&g_cnt[i2], 1);
        g_slot[i2][p2] = n * 2 + 1; g_gate[i2][p2] = w2;
    }
}

__global__ void k_cvt_x(const float* __restrict__ x) {
    size_t i = (size_t)blockIdx.x * blockDim.x + threadIdx.x;
    float4 v = ((const float4*)x)[i];
    float vv[4] = {v.x, v.y, v.z, v.w};
    __nv_bfloat16 h[4], l[4];
#pragma unroll
    for (int q = 0; q < 4; q++) {
        h[q] = __float2bfloat16(vv[q]);
        l[q] = __float2bfloat16(vv[q] - __bfloat162float(h[q]));
    }
    ((uint2*)g_xhi)[i] = *(uint2*)h;
    ((uint2*)g_xlo)[i] = *(uint2*)l;
}

// transpose + split-convert: src [e][R][C] fp32 -> dst [e][C][R] bf16 hi/lo
__global__ void k_cvtT(const float* __restrict__ src, int which, int R, int C) {
    __nv_bfloat16 *dhi, *dlo;
    if (which == 0)      { dhi = g_w1hi; dlo = g_w1lo; }
    else if (which == 1) { dhi = g_w3hi; dlo = g_w3lo; }
    else                 { dhi = g_w2hi; dlo = g_w2lo; }
    __shared__ float t[32][33];
    int e = blockIdx.z;
    int r0 = blockIdx.x * 32, c0 = blockIdx.y * 32;
    const float* s = src + ((size_t)e * R + r0) * C + c0;
    int tx = threadIdx.x, ty = threadIdx.y;
#pragma unroll
    for (int i = 0; i < 32; i += 8) t[ty + i][tx] = s[(size_t)(ty + i) * C + tx];
    __syncthreads();
    size_t dbase = ((size_t)e * C + c0) * R + r0;
#pragma unroll
    for (int i = 0; i < 32; i += 8) {
        float v = t[tx][ty + i];
        __nv_bfloat16 h = __float2bfloat16(v);
        size_t o = dbase + (size_t)(ty + i) * R + tx;
        dhi[o] = h;
        dlo[o] = __float2bfloat16(v - __bfloat162float(h));
    }
}

// ---------------- GEMM1: H = silu(X W1) * (X W3) -----------------------------
// CTA tile 128m x 64n, k-chunk 32. smem rows packed [hi 64B | lo 64B] = 128B.
// stage: A 16KB + B(W1,W3) 16KB = 32KB, double buffered.
#define GS_SMEM (1024 + 2*32768)

__global__ __launch_bounds__(256, 2) void k_gemm1() {
    int e = blockIdx.z;
    int cnt = g_cnt[e];
    int m0 = blockIdx.x * 128;
    if (m0 >= cnt) return;
    int n0 = blockIdx.y * 64;

    extern __shared__ char smem[];
    int* rows = (int*)smem;
    uint32_t sb = s2u(smem);
    uint32_t sA[2] = {sb + 1024, sb + 1024 + 32768};
    uint32_t sB[2] = {sb + 1024 + 16384, sb + 1024 + 32768 + 16384};
    int tid = threadIdx.x, lane = tid & 31, wid = tid >> 5;

    if (tid < 128) {
        int m = m0 + tid;
        rows[tid] = g_slot[e][m < cnt ? m : cnt - 1];
    }
    __syncthreads();

    const __nv_bfloat16* w1h = g_w1hi + (size_t)e * DINTER * DMODEL;
    const __nv_bfloat16* w1l = g_w1lo + (size_t)e * DINTER * DMODEL;
    const __nv_bfloat16* w3h = g_w3hi + (size_t)e * DINTER * DMODEL;
    const __nv_bfloat16* w3l = g_w3lo + (size_t)e * DINTER * DMODEL;

    auto load_stage = [&](int it) {
        int buf = it & 1;
        int k0 = it * 32;
        uint32_t a = sA[buf], b = sB[buf];
#pragma unroll
        for (int q = 0; q < 4; q++) {          // A: 128 rows x 8 chunks
            int i = tid + q * 256;
            int r = i >> 3, c = i & 7;
            const __nv_bfloat16* src = (c < 4 ? g_xhi : g_xlo)
                + (size_t)(rows[r] >> 1) * DMODEL + k0 + (c & 3) * 8;
            cp16(a + SWZ(r * 128 + c * 16), src);
        }
#pragma unroll
        for (int q = 0; q < 4; q++) {          // B: 2 blocks x 64 rows x 8 chunks
            int i = tid + q * 256;
            int blk = i >> 9;
            int r = (i >> 3) & 63, c = i & 7;
            const __nv_bfloat16* base = blk ? (c < 4 ? w3h : w3l) : (c < 4 ? w1h : w1l);
            const __nv_bfloat16* src = base + (size_t)(n0 + r) * DMODEL + k0 + (c & 3) * 8;
            cp16(b + blk * 8192 + SWZ(r * 128 + c * 16), src);
        }
        CP_COMMIT();
    };

    float acc1[2][4][4] = {}, acc3[2][4][4] = {};
    int m0w = (wid & 3) * 32, n0w = (wid >> 2) * 32;

    load_stage(0);
    load_stage(1);
    const int ITERS = DMODEL / 32;   // 32
    for (int it = 0; it < ITERS; ++it) {
        int buf = it & 1;
        if (it + 1 < ITERS) CP_WAIT1(); else CP_WAIT0();
        __syncthreads();
        uint32_t a = sA[buf], b = sB[buf];
#pragma unroll
        for (int ks = 0; ks < 2; ++ks) {
            uint32_t ah[2][4], al[2][4];
            int colh = ks * 32 + ((lane >> 4) << 4);
#pragma unroll
            for (int i = 0; i < 2; i++) {
                int row = m0w + i * 16 + (lane & 15);
                ldsm4(ah[i][0], ah[i][1], ah[i][2], ah[i][3], a + SWZ(row * 128 + colh));
                ldsm4(al[i][0], al[i][1], al[i][2], al[i][3], a + SWZ(row * 128 + 64 + colh));
            }
            int colb = ks * 32 + ((lane & 8) << 1);
#pragma unroll
            for (int j = 0; j < 4; j++) {
                int rn = n0w + j * 8 + (lane & 7);
                uint32_t b1h[2], b1l[2], b3h[2], b3l[2];
                ldsm2(b1h[0], b1h[1], b + SWZ(rn * 128 + colb));
                ldsm2(b1l[0], b1l[1], b + SWZ(rn * 128 + 64 + colb));
                ldsm2(b3h[0], b3h[1], b + 8192 + SWZ(rn * 128 + colb));
                ldsm2(b3l[0], b3l[1], b + 8192 + SWZ(rn * 128 + 64 + colb));
#pragma unroll
                for (int i = 0; i < 2; i++) {
                    mma16816(acc1[i][j], ah[i], b1h);
                    mma16816(acc1[i][j], ah[i], b1l);
                    mma16816(acc1[i][j], al[i], b1h);
                    mma16816(acc3[i][j], ah[i], b3h);
                    mma16816(acc3[i][j], ah[i], b3l);
                    mma16816(acc3[i][j], al[i], b3h);
                }
            }
        }
        __syncthreads();
        if (it + 2 < ITERS) load_stage(it + 2);
    }

    // epilogue: silu(acc1)*acc3, split to bf16 hi/lo, store H
    int gr = lane >> 2, gc = (lane & 3) * 2;
#pragma unroll
    for (int i = 0; i < 2; i++) {
#pragma unroll
        for (int half = 0; half < 2; half++) {
            int m = m0w + i * 16 + gr + half * 8;
            if (m0 + m < cnt) {
                int slot = rows[m];
                __nv_bfloat16* ph = g_hhi + (size_t)slot * DINTER + n0 + n0w;
                __nv_bfloat16* pl = g_hlo + (size_t)slot * DINTER + n0 + n0w;
#pragma unroll
                for (int j = 0; j < 4; j++) {
                    float a0 = acc1[i][j][half * 2 + 0], a1 = acc1[i][j][half * 2 + 1];
                    float c0 = acc3[i][j][half * 2 + 0], c1 = acc3[i][j][half * 2 + 1];
                    float s0 = a0 / (1.f + __expf(-a0)) * c0;
                    float s1 = a1 / (1.f + __expf(-a1)) * c1;
                    __nv_bfloat16 h0 = __float2bfloat16(s0), h1 = __float2bfloat16(s1);
                    union { __nv_bfloat16 b[2]; uint32_t u; } uh, ul;
                    uh.b[0] = h0; uh.b[1] = h1;
                    ul.b[0] = __float2bfloat16(s0 - __bfloat162float(h0));
                    ul.b[1] = __float2bfloat16(s1 - __bfloat162float(h1));
                    *(uint32_t*)(ph + j * 8 + gc) = uh.u;
                    *(uint32_t*)(pl + j * 8 + gc) = ul.u;
                }
            }
        }
    }
}

// ---------------- GEMM2: out += gate * (H W2) --------------------------------
// CTA tile 128m x 128n, k-chunk 32, 22 iters. warp = 32m x 64n.
__global__ __launch_bounds__(256, 2) void k_gemm2(float* __restrict__ out) {
    int e = blockIdx.z;
    int cnt = g_cnt[e];
    int m0 = blockIdx.x * 128;
    if (m0 >= cnt) return;
    int n0 = blockIdx.y * 128;

    extern __shared__ char smem[];
    int*   rows  = (int*)smem;
    float* gates = (float*)(smem + 512);
    uint32_t sb = s2u(smem);
    uint32_t sA[2] = {sb + 1024, sb + 1024 + 32768};
    uint32_t sB[2] = {sb + 1024 + 16384, sb + 1024 + 32768 + 16384};
    int tid = threadIdx.x, lane = tid & 31, wid = tid >> 5;

    if (tid < 128) {
        int m = m0 + tid;
        int mm = m < cnt ? m : cnt - 1;
        rows[tid]  = g_slot[e][mm];
        gates[tid] = g_gate[e][mm];
    }
    __syncthreads();

    const __nv_bfloat16* w2h = g_w2hi + (size_t)e * DMODEL * DINTER;
    const __nv_bfloat16* w2l = g_w2lo + (size_t)e * DMODEL * DINTER;

    auto load_stage = [&](int it) {
        int buf = it & 1;
        int k0 = it * 32;
        uint32_t a = sA[buf], b = sB[buf];
#pragma unroll
        for (int q = 0; q < 4; q++) {          // A: 128 gathered H rows
            int i = tid + q * 256;
            int r = i >> 3, c = i & 7;
            const __nv_bfloat16* src = (c < 4 ? g_hhi : g_hlo)
                + (size_t)rows[r] * DINTER + k0 + (c & 3) * 8;
            cp16(a + SWZ(r * 128 + c * 16), src);
        }
#pragma unroll
        for (int q = 0; q < 4; q++) {          // B: 128 n-rows of W2T
            int i = tid + q * 256;
            int r = i >> 3, c = i & 7;
            const __nv_bfloat16* src = (c < 4 ? w2h : w2l)
                + (size_t)(n0 + r) * DINTER + k0 + (c & 3) * 8;
            cp16(b + SWZ(r * 128 + c * 16), src);
        }
        CP_COMMIT();
    };

    float acc[2][8][4] = {};
    int m0w = (wid & 3) * 32, n0w = (wid >> 2) * 64;

    load_stage(0);
    load_stage(1);
    const int ITERS = DINTER / 32;   // 22
    for (int it = 0; it < ITERS; ++it) {
        int buf = it & 1;
        if (it + 1 < ITERS) CP_WAIT1(); else CP_WAIT0();
        __syncthreads();
        uint32_t a = sA[buf], b = sB[buf];
#pragma unroll
        for (int ks = 0; ks < 2; ++ks) {
            uint32_t ah[2][4], al[2][4];
            int colh = ks * 32 + ((lane >> 4) << 4);
#pragma unroll
            for (int i = 0; i < 2; i++) {
                int row = m0w + i * 16 + (lane & 15);
                ldsm4(ah[i][0], ah[i][1], ah[i][2], ah[i][3], a + SWZ(row * 128 + colh));
                ldsm4(al[i][0], al[i][1], al[i][2], al[i][3], a + SWZ(row * 128 + 64 + colh));
            }
            int colb = ks * 32 + ((lane & 8) << 1);
#pragma unroll
            for (int j = 0; j < 8; j++) {
                int rn = n0w + j * 8 + (lane & 7);
                uint32_t bh[2], bl[2];
                ldsm2(bh[0], bh[1], b + SWZ(rn * 128 + colb));
                ldsm2(bl[0], bl[1], b + SWZ(rn * 128 + 64 + colb));
#pragma unroll
                for (int i = 0; i < 2; i++) {
                    mma16816(acc[i][j], ah[i], bh);
                    mma16816(acc[i][j], ah[i], bl);
                    mma16816(acc[i][j], al[i], bh);
                }
            }
        }
        __syncthreads();
        if (it + 2 < ITERS) load_stage(it + 2);
    }

    int gr = lane >> 2, gc = (lane & 3) * 2;
#pragma unroll
    for (int i = 0; i < 2; i++) {
#pragma unroll
        for (int half = 0; half < 2; half++) {
            int m = m0w + i * 16 + gr + half * 8;
            if (m0 + m < cnt) {
                int tok = rows[m] >> 1;
                float g = gates[m];
                float* op = out + (size_t)tok * DMODEL + n0 + n0w;
#pragma unroll
                for (int j = 0; j < 8; j++) {
                    atomicAdd(op + j * 8 + gc + 0, g * acc[i][j][half * 2 + 0]);
                    atomicAdd(op + j * 8 + gc + 1, g * acc[i][j][half * 2 + 1]);
                }
            }
        }
    }
}

// ---------------------------------------------------------------------------
extern "C" void kernel_launch(void* const* d_in, const int* in_sizes, int n_in,
                              void* d_out, int out_size) {
    const float* x  = (const float*)d_in[0];
    const float* Wg = (const float*)d_in[1];
    const float* W1 = (const float*)d_in[2];
    const float* W2 = (const float*)d_in[3];
    const float* W3 = (const float*)d_in[4];
    float* out = (float*)d_out;

    cudaFuncSetAttribute(k_gemm1, cudaFuncAttributeMaxDynamicSharedMemorySize, GS_SMEM);
    cudaFuncSetAttribute(k_gemm2, cudaFuncAttributeMaxDynamicSharedMemorySize, GS_SMEM);

    cudaMemsetAsync(d_out, 0, (size_t)out_size * sizeof(float), 0);
    k_reset<<<1, 32>>>();
    k_router<<<NTOK, 128>>>(x, Wg);
    k_cvt_x<<<(NTOK * DMODEL / 4) / 256, 256>>>(x);
    dim3 tb(32, 8);
    k_cvtT<<<dim3(DMODEL / 32, DINTER / 32, NEXP), tb>>>(W1, 0, DMODEL, DINTER);
    k_cvtT<<<dim3(DMODEL / 32, DINTER / 32, NEXP), tb>>>(W3, 1, DMODEL, DINTER);
    k_cvtT<<<dim3(DINTER / 32, DMODEL / 32, NEXP), tb>>>(W2, 2, DINTER, DMODEL);

    k_gemm1<<<dim3(NTOK / 128, DINTER / 64, NEXP), 256, GS_SMEM>>>();
    k_gemm2<<<dim3(NTOK / 128, DMODEL / 128, NEXP), 256, GS_SMEM>>>(out);
}

// round 8
// speedup vs baseline: 2.8965x; 1.3212x over previous
#include <cuda_runtime.h>
#include <cuda_fp16.h>
#include <math.h>
#include <stdint.h>

#define NTOK   4096
#define DMODEL 1024
#define DINTER 704
#define NEXP   16
#define NSLOT  (NTOK*2)

// ---------------- device scratch (no allocations allowed) -------------------
__device__ int   g_cnt[NEXP];
__device__ int   g_slot[NEXP][NTOK];
__device__ float g_gate[NEXP][NTOK];

__device__ __align__(16) __half g_xhi[(size_t)NTOK*DMODEL];
__device__ __align__(16) __half g_xlo[(size_t)NTOK*DMODEL];
// weights transposed to K-major, single fp16: W1T/W3T [e][704][1024], W2T [e][1024][704]
__device__ __align__(16) __half g_w1[(size_t)NEXP*DINTER*DMODEL];
__device__ __align__(16) __half g_w3[(size_t)NEXP*DINTER*DMODEL];
__device__ __align__(16) __half g_w2[(size_t)NEXP*DMODEL*DINTER];
__device__ __align__(16) __half g_hhi[(size_t)NSLOT*DINTER];
__device__ __align__(16) __half g_hlo[(size_t)NSLOT*DINTER];

// ---------------- PTX helpers ----------------------------------------------
__device__ __forceinline__ uint32_t s2u(const void* p) {
    uint32_t a;
    asm("{ .reg .u64 t; cvta.to.shared.u64 t, %1; cvt.u32.u64 %0, t; }" : "=r"(a) : "l"(p));
    return a;
}
#define SWZ(o) ((o) ^ (((o) >> 3) & 0x70))

__device__ __forceinline__ void cp16(uint32_t dst, const void* src) {
    asm volatile("cp.async.cg.shared.global [%0], [%1], 16;" :: "r"(dst), "l"(src));
}
#define CP_COMMIT() asm volatile("cp.async.commit_group;" ::: "memory")
#define CP_WAIT1()  asm volatile("cp.async.wait_group 1;" ::: "memory")
#define CP_WAIT0()  asm volatile("cp.async.wait_group 0;" ::: "memory")

__device__ __forceinline__ void ldsm4(uint32_t& r0, uint32_t& r1, uint32_t& r2, uint32_t& r3,
                                      uint32_t addr) {
    asm volatile("ldmatrix.sync.aligned.m8n8.x4.shared.b16 {%0,%1,%2,%3}, [%4];"
                 : "=r"(r0), "=r"(r1), "=r"(r2), "=r"(r3) : "r"(addr));
}
__device__ __forceinline__ void ldsm2(uint32_t& r0, uint32_t& r1, uint32_t addr) {
    asm volatile("ldmatrix.sync.aligned.m8n8.x2.shared.b16 {%0,%1}, [%2];"
                 : "=r"(r0), "=r"(r1) : "r"(addr));
}
__device__ __forceinline__ void mma16816(float* d, const uint32_t* a, const uint32_t* b) {
    asm volatile(
        "mma.sync.aligned.m16n8k16.row.col.f32.f16.f16.f32 "
        "{%0,%1,%2,%3},{%4,%5,%6,%7},{%8,%9},{%0,%1,%2,%3};"
        : "+f"(d[0]), "+f"(d[1]), "+f"(d[2]), "+f"(d[3])
        : "r"(a[0]), "r"(a[1]), "r"(a[2]), "r"(a[3]), "r"(b[0]), "r"(b[1]));
}

// ---------------- small kernels ----------------------------------------------
__global__ void k_reset() {
    if (threadIdx.x < NEXP) g_cnt[threadIdx.x] = 0;
}

__global__ void k_router(const float* __restrict__ x, const float* __restrict__ Wg) {
    int n = blockIdx.x;
    const float* xr = x + (size_t)n * DMODEL;
    int tid = threadIdx.x;
    int e = tid >> 3, l = tid & 7;
    const float* wr = Wg + e * DMODEL;
    float s = 0.f;
#pragma unroll 8
    for (int d = l; d < DMODEL; d += 8) s += xr[d] * wr[d];
    s += __shfl_down_sync(0xffffffffu, s, 4);
    s += __shfl_down_sync(0xffffffffu, s, 2);
    s += __shfl_down_sync(0xffffffffu, s, 1);
    __shared__ float logits[NEXP];
    if (l == 0) logits[e] = s;
    __syncthreads();
    if (tid == 0) {
        int i1 = 0; float v1 = logits[0];
#pragma unroll
        for (int j = 1; j < NEXP; j++) if (logits[j] > v1) { v1 = logits[j]; i1 = j; }
        int i2 = -1; float v2 = -3.4e38f;
#pragma unroll
        for (int j = 0; j < NEXP; j++) if (j != i1 && logits[j] > v2) { v2 = logits[j]; i2 = j; }
        float w1 = 1.f / (1.f + expf(v2 - v1));
        float w2 = 1.f - w1;
        int p1 = atomicAdd(&g_cnt[i1], 1);
        g_slot[i1][p1] = n * 2;     g_gate[i1][p1] = w1;
        int p2 = atomicAdd(&g_cnt[i2], 1);
        g_slot[i2][p2] = n * 2 + 1; g_gate[i2][p2] = w2;
    }
}

__global__ void k_cvt_x(const float* __restrict__ x) {
    size_t i = (size_t)blockIdx.x * blockDim.x + threadIdx.x;
    float4 v = ((const float4*)x)[i];
    float vv[4] = {v.x, v.y, v.z, v.w};
    __half h[4], l[4];
#pragma unroll
    for (int q = 0; q < 4; q++) {
        h[q] = __float2half(vv[q]);
        l[q] = __float2half(vv[q] - __half2float(h[q]));
    }
    ((uint2*)g_xhi)[i] = *(uint2*)h;
    ((uint2*)g_xlo)[i] = *(uint2*)l;
}

// transpose + convert: src [e][R][C] fp32 -> dst [e][C][R] fp16
__global__ void k_cvtT(const float* __restrict__ src, int which, int R, int C) {
    __half* dst;
    if (which == 0)      dst = g_w1;
    else if (which == 1) dst = g_w3;
    else                 dst = g_w2;
    __shared__ float t[32][33];
    int e = blockIdx.z;
    int r0 = blockIdx.x * 32, c0 = blockIdx.y * 32;
    const float* s = src + ((size_t)e * R + r0) * C + c0;
    int tx = threadIdx.x, ty = threadIdx.y;
#pragma unroll
    for (int i = 0; i < 32; i += 8) t[ty + i][tx] = s[(size_t)(ty + i) * C + tx];
    __syncthreads();
    size_t dbase = ((size_t)e * C + c0) * R + r0;
#pragma unroll
    for (int i = 0; i < 32; i += 8)
        dst[dbase + (size_t)(ty + i) * R + tx] = __float2half(t[tx][ty + i]);
}

// ---------------- GEMM1: H = silu(X W1) * (X W3) -----------------------------
// CTA 128m x 64n, k-chunk 64. Stage: A-hi 16K | A-lo 16K | B-w1 8K | B-w3 8K = 48KB x2.
#define G_STAGE 49152
#define G_SMEM  (1024 + 2*G_STAGE)

__global__ __launch_bounds__(256, 2) void k_gemm1() {
    int e = blockIdx.z;
    int cnt = g_cnt[e];
    int m0 = blockIdx.x * 128;
    if (m0 >= cnt) return;
    int n0 = blockIdx.y * 64;

    extern __shared__ char smem[];
    int* rows = (int*)smem;
    uint32_t sb = s2u(smem);
    uint32_t st[2] = {sb + 1024, sb + 1024 + G_STAGE};
    int tid = threadIdx.x, lane = tid & 31, wid = tid >> 5;

    if (tid < 128) {
        int m = m0 + tid;
        rows[tid] = g_slot[e][m < cnt ? m : cnt - 1];
    }
    __syncthreads();

    const __half* w1 = g_w1 + (size_t)e * DINTER * DMODEL;
    const __half* w3 = g_w3 + (size_t)e * DINTER * DMODEL;

    auto load_stage = [&](int it) {
        uint32_t base = st[it & 1];
        int k0 = it * 64;
#pragma unroll
        for (int q = 0; q < 8; q++) {          // A: 128 rows x 16 chunks (hi 8 | lo 8)
            int i = tid + q * 256;
            int r = i >> 4, c = i & 15;
            const __half* src = (c < 8 ? g_xhi : g_xlo)
                + (size_t)(rows[r] >> 1) * DMODEL + k0 + (c & 7) * 8;
            cp16(base + (c < 8 ? 0 : 16384) + SWZ(r * 128 + (c & 7) * 16), src);
        }
#pragma unroll
        for (int q = 0; q < 4; q++) {          // B: 2 mats x 64 rows x 8 chunks
            int i = tid + q * 256;
            int r = i >> 3, c = i & 7;
            int blk = r >> 6, rr = r & 63;
            const __half* src = (blk ? w3 : w1) + (size_t)(n0 + rr) * DMODEL + k0 + c * 8;
            cp16(base + 32768 + blk * 8192 + SWZ(rr * 128 + c * 16), src);
        }
        CP_COMMIT();
    };

    float acc1[2][4][4] = {}, acc3[2][4][4] = {};
    int m0w = (wid & 3) * 32, n0w = (wid >> 2) * 32;

    load_stage(0);
    load_stage(1);
    const int ITERS = DMODEL / 64;   // 16
    for (int it = 0; it < ITERS; ++it) {
        if (it + 1 < ITERS) CP_WAIT1(); else CP_WAIT0();
        __syncthreads();
        uint32_t a = st[it & 1], b = st[it & 1] + 32768;
#pragma unroll
        for (int ks = 0; ks < 4; ++ks) {
            uint32_t ah[2][4], al[2][4];
            int colh = ks * 32 + ((lane >> 4) << 4);
#pragma unroll
            for (int i = 0; i < 2; i++) {
                int row = m0w + i * 16 + (lane & 15);
                ldsm4(ah[i][0], ah[i][1], ah[i][2], ah[i][3], a + SWZ(row * 128 + colh));
                ldsm4(al[i][0], al[i][1], al[i][2], al[i][3], a + 16384 + SWZ(row * 128 + colh));
            }
            int colb = ks * 32 + ((lane & 8) << 1);
#pragma unroll
            for (int j = 0; j < 4; j++) {
                int rn = n0w + j * 8 + (lane & 7);
                uint32_t b1[2], b3[2];
                ldsm2(b1[0], b1[1], b + SWZ(rn * 128 + colb));
                ldsm2(b3[0], b3[1], b + 8192 + SWZ(rn * 128 + colb));
#pragma unroll
                for (int i = 0; i < 2; i++) {
                    mma16816(acc1[i][j], ah[i], b1);
                    mma16816(acc1[i][j], al[i], b1);
                    mma16816(acc3[i][j], ah[i], b3);
                    mma16816(acc3[i][j], al[i], b3);
                }
            }
        }
        __syncthreads();
        if (it + 2 < ITERS) load_stage(it + 2);
    }

    // epilogue: silu(acc1)*acc3, split fp16 hi/lo, store H
    int gr = lane >> 2, gc = (lane & 3) * 2;
#pragma unroll
    for (int i = 0; i < 2; i++) {
#pragma unroll
        for (int half = 0; half < 2; half++) {
            int m = m0w + i * 16 + gr + half * 8;
            if (m0 + m < cnt) {
                int slot = rows[m];
                __half* ph = g_hhi + (size_t)slot * DINTER + n0 + n0w;
                __half* pl = g_hlo + (size_t)slot * DINTER + n0 + n0w;
#pragma unroll
                for (int j = 0; j < 4; j++) {
                    float a0 = acc1[i][j][half * 2 + 0], a1 = acc1[i][j][half * 2 + 1];
                    float c0 = acc3[i][j][half * 2 + 0], c1 = acc3[i][j][half * 2 + 1];
                    float s0 = a0 / (1.f + __expf(-a0)) * c0;
                    float s1 = a1 / (1.f + __expf(-a1)) * c1;
                    __half h0 = __float2half(s0), h1 = __float2half(s1);
                    union { __half b[2]; uint32_t u; } uh, ul;
                    uh.b[0] = h0; uh.b[1] = h1;
                    ul.b[0] = __float2half(s0 - __half2float(h0));
                    ul.b[1] = __float2half(s1 - __half2float(h1));
                    *(uint32_t*)(ph + j * 8 + gc) = uh.u;
                    *(uint32_t*)(pl + j * 8 + gc) = ul.u;
                }
            }
        }
    }
}

// ---------------- GEMM2: out += gate * (H W2) --------------------------------
// CTA 128m x 128n, k-chunk 64, 11 iters. warp = 32m x 64n.
__global__ __launch_bounds__(256, 2) void k_gemm2(float* __restrict__ out) {
    int e = blockIdx.z;
    int cnt = g_cnt[e];
    int m0 = blockIdx.x * 128;
    if (m0 >= cnt) return;
    int n0 = blockIdx.y * 128;

    extern __shared__ char smem[];
    int*   rows  = (int*)smem;
    float* gates = (float*)(smem + 512);
    uint32_t sb = s2u(smem);
    uint32_t st[2] = {sb + 1024, sb + 1024 + G_STAGE};
    int tid = threadIdx.x, lane = tid & 31, wid = tid >> 5;

    if (tid < 128) {
        int m = m0 + tid;
        int mm = m < cnt ? m : cnt - 1;
        rows[tid]  = g_slot[e][mm];
        gates[tid] = g_gate[e][mm];
    }
    __syncthreads();

    const __half* w2 = g_w2 + (size_t)e * DMODEL * DINTER;

    auto load_stage = [&](int it) {
        uint32_t base = st[it & 1];
        int k0 = it * 64;
#pragma unroll
        for (int q = 0; q < 8; q++) {          // A: 128 gathered H rows, hi|lo
            int i = tid + q * 256;
            int r = i >> 4, c = i & 15;
            const __half* src = (c < 8 ? g_hhi : g_hlo)
                + (size_t)rows[r] * DINTER + k0 + (c & 7) * 8;
            cp16(base + (c < 8 ? 0 : 16384) + SWZ(r * 128 + (c & 7) * 16), src);
        }
#pragma unroll
        for (int q = 0; q < 4; q++) {          // B: 128 n-rows of W2T
            int i = tid + q * 256;
            int r = i >> 3, c = i & 7;
            const __half* src = w2 + (size_t)(n0 + r) * DINTER + k0 + c * 8;
            cp16(base + 32768 + SWZ(r * 128 + c * 16), src);
        }
        CP_COMMIT();
    };

    float acc[2][8][4] = {};
    int m0w = (wid & 3) * 32, n0w = (wid >> 2) * 64;

    load_stage(0);
    load_stage(1);
    const int ITERS = DINTER / 64;   // 11
    for (int it = 0; it < ITERS; ++it) {
        if (it + 1 < ITERS) CP_WAIT1(); else CP_WAIT0();
        __syncthreads();
        uint32_t a = st[it & 1], b = st[it & 1] + 32768;
#pragma unroll
        for (int ks = 0; ks < 4; ++ks) {
            uint32_t ah[2][4], al[2][4];
            int colh = ks * 32 + ((lane >> 4) << 4);
#pragma unroll
            for (int i = 0; i < 2; i++) {
                int row = m0w + i * 16 + (lane & 15);
                ldsm4(ah[i][0], ah[i][1], ah[i][2], ah[i][3], a + SWZ(row * 128 + colh));
                ldsm4(al[i][0], al[i][1], al[i][2], al[i][3], a + 16384 + SWZ(row * 128 + colh));
            }
            int colb = ks * 32 + ((lane & 8) << 1);
#pragma unroll
            for (int j = 0; j < 8; j++) {
                int rn = n0w + j * 8 + (lane & 7);
                uint32_t bw[2];
                ldsm2(bw[0], bw[1], b + SWZ(rn * 128 + colb));
#pragma unroll
                for (int i = 0; i < 2; i++) {
                    mma16816(acc[i][j], ah[i], bw);
                    mma16816(acc[i][j], al[i], bw);
                }
            }
        }
        __syncthreads();
        if (it + 2 < ITERS) load_stage(it + 2);
    }

    int gr = lane >> 2, gc = (lane & 3) * 2;
#pragma unroll
    for (int i = 0; i < 2; i++) {
#pragma unroll
        for (int half = 0; half < 2; half++) {
            int m = m0w + i * 16 + gr + half * 8;
            if (m0 + m < cnt) {
                int tok = rows[m] >> 1;
                float g = gates[m];
                float* op = out + (size_t)tok * DMODEL + n0 + n0w;
#pragma unroll
                for (int j = 0; j < 8; j++) {
                    atomicAdd(op + j * 8 + gc + 0, g * acc[i][j][half * 2 + 0]);
                    atomicAdd(op + j * 8 + gc + 1, g * acc[i][j][half * 2 + 1]);
                }
            }
        }
    }
}

// ---------------------------------------------------------------------------
extern "C" void kernel_launch(void* const* d_in, const int* in_sizes, int n_in,
                              void* d_out, int out_size) {
    const float* x  = (const float*)d_in[0];
    const float* Wg = (const float*)d_in[1];
    const float* W1 = (const float*)d_in[2];
    const float* W2 = (const float*)d_in[3];
    const float* W3 = (const float*)d_in[4];
    float* out = (float*)d_out;

    cudaFuncSetAttribute(k_gemm1, cudaFuncAttributeMaxDynamicSharedMemorySize, G_SMEM);
    cudaFuncSetAttribute(k_gemm2, cudaFuncAttributeMaxDynamicSharedMemorySize, G_SMEM);

    cudaMemsetAsync(d_out, 0, (size_t)out_size * sizeof(float), 0);
    k_reset<<<1, 32>>>();
    k_router<<<NTOK, 128>>>(x, Wg);
    k_cvt_x<<<(NTOK * DMODEL / 4) / 256, 256>>>(x);
    dim3 tb(32, 8);
    k_cvtT<<<dim3(DMODEL / 32, DINTER / 32, NEXP), tb>>>(W1, 0, DMODEL, DINTER);
    k_cvtT<<<dim3(DMODEL / 32, DINTER / 32, NEXP), tb>>>(W3, 1, DMODEL, DINTER);
    k_cvtT<<<dim3(DINTER / 32, DMODEL / 32, NEXP), tb>>>(W2, 2, DINTER, DMODEL);

    k_gemm1<<<dim3(NTOK / 128, DINTER / 64, NEXP), 256, G_SMEM>>>();
    k_gemm2<<<dim3(NTOK / 128, DMODEL / 128, NEXP), 256, G_SMEM>>>(out);
}

// round 10
// speedup vs baseline: 4.2162x; 1.4556x over previous
#include <cuda_runtime.h>
#include <cuda_fp16.h>
#include <math.h>
#include <stdint.h>

#define NTOK   4096
#define DMODEL 1024
#define DINTER 704
#define NEXP   16
#define NSLOT  (NTOK*2)

// ---------------- device scratch (no allocations allowed) -------------------
__device__ int   g_cnt[NEXP];
__device__ int   g_slot[NEXP][NTOK];
__device__ float g_gate[NEXP][NTOK];

__device__ __align__(16) __half g_x[(size_t)NTOK*DMODEL];
// weights transposed to K-major, fp16: W1T/W3T [e][704][1024], W2T [e][1024][704]
__device__ __align__(16) __half g_w1[(size_t)NEXP*DINTER*DMODEL];
__device__ __align__(16) __half g_w3[(size_t)NEXP*DINTER*DMODEL];
__device__ __align__(16) __half g_w2[(size_t)NEXP*DMODEL*DINTER];
__device__ __align__(16) __half g_h[(size_t)NSLOT*DINTER];

// ---------------- PTX helpers ----------------------------------------------
__device__ __forceinline__ uint32_t s2u(const void* p) {
    uint32_t a;
    asm("{ .reg .u64 t; cvta.to.shared.u64 t, %1; cvt.u32.u64 %0, t; }" : "=r"(a) : "l"(p));
    return a;
}
#define SWZ(o) ((o) ^ (((o) >> 3) & 0x70))

__device__ __forceinline__ void cp16(uint32_t dst, const void* src) {
    asm volatile("cp.async.cg.shared.global [%0], [%1], 16;" :: "r"(dst), "l"(src));
}
#define CP_COMMIT() asm volatile("cp.async.commit_group;" ::: "memory")
#define CP_WAIT1()  asm volatile("cp.async.wait_group 1;" ::: "memory")
#define CP_WAIT0()  asm volatile("cp.async.wait_group 0;" ::: "memory")

__device__ __forceinline__ void ldsm4(uint32_t& r0, uint32_t& r1, uint32_t& r2, uint32_t& r3,
                                      uint32_t addr) {
    asm volatile("ldmatrix.sync.aligned.m8n8.x4.shared.b16 {%0,%1,%2,%3}, [%4];"
                 : "=r"(r0), "=r"(r1), "=r"(r2), "=r"(r3) : "r"(addr));
}
__device__ __forceinline__ void mma16816(float* d, const uint32_t* a, const uint32_t* b) {
    asm volatile(
        "mma.sync.aligned.m16n8k16.row.col.f32.f16.f16.f32 "
        "{%0,%1,%2,%3},{%4,%5,%6,%7},{%8,%9},{%0,%1,%2,%3};"
        : "+f"(d[0]), "+f"(d[1]), "+f"(d[2]), "+f"(d[3])
        : "r"(a[0]), "r"(a[1]), "r"(a[2]), "r"(a[3]), "r"(b[0]), "r"(b[1]));
}

// ---------------- small kernels ----------------------------------------------
__global__ void k_reset() {
    if (threadIdx.x < NEXP) g_cnt[threadIdx.x] = 0;
}

__global__ void k_router(const float* __restrict__ x, const float* __restrict__ Wg) {
    int n = blockIdx.x;
    const float* xr = x + (size_t)n * DMODEL;
    int tid = threadIdx.x;
    int e = tid >> 3, l = tid & 7;
    const float* wr = Wg + e * DMODEL;
    float s = 0.f;
#pragma unroll 8
    for (int d = l; d < DMODEL; d += 8) s += xr[d] * wr[d];
    s += __shfl_down_sync(0xffffffffu, s, 4);
    s += __shfl_down_sync(0xffffffffu, s, 2);
    s += __shfl_down_sync(0xffffffffu, s, 1);
    __shared__ float logits[NEXP];
    if (l == 0) logits[e] = s;
    __syncthreads();
    if (tid == 0) {
        int i1 = 0; float v1 = logits[0];
#pragma unroll
        for (int j = 1; j < NEXP; j++) if (logits[j] > v1) { v1 = logits[j]; i1 = j; }
        int i2 = -1; float v2 = -3.4e38f;
#pragma unroll
        for (int j = 0; j < NEXP; j++) if (j != i1 && logits[j] > v2) { v2 = logits[j]; i2 = j; }
        float w1 = 1.f / (1.f + expf(v2 - v1));
        float w2 = 1.f - w1;
        int p1 = atomicAdd(&g_cnt[i1], 1);
        g_slot[i1][p1] = n * 2;     g_gate[i1][p1] = w1;
        int p2 = atomicAdd(&g_cnt[i2], 1);
        g_slot[i2][p2] = n * 2 + 1; g_gate[i2][p2] = w2;
    }
}

__global__ void k_cvt_x(const float* __restrict__ x) {
    size_t i = (size_t)blockIdx.x * blockDim.x + threadIdx.x;
    float4 v = ((const float4*)x)[i];
    __half h[4] = {__float2half(v.x), __float2half(v.y), __float2half(v.z), __float2half(v.w)};
    ((uint2*)g_x)[i] = *(uint2*)h;
}

// transpose + convert: src [e][R][C] fp32 -> dst [e][C][R] fp16
__global__ void k_cvtT(const float* __restrict__ src, int which, int R, int C) {
    __half* dst;
    if (which == 0)      dst = g_w1;
    else if (which == 1) dst = g_w3;
    else                 dst = g_w2;
    __shared__ float t[32][33];
    int e = blockIdx.z;
    int r0 = blockIdx.x * 32, c0 = blockIdx.y * 32;
    const float* s = src + ((size_t)e * R + r0) * C + c0;
    int tx = threadIdx.x, ty = threadIdx.y;
#pragma unroll
    for (int i = 0; i < 32; i += 8) t[ty + i][tx] = s[(size_t)(ty + i) * C + tx];
    __syncthreads();
    size_t dbase = ((size_t)e * C + c0) * R + r0;
#pragma unroll
    for (int i = 0; i < 32; i += 8)
        dst[dbase + (size_t)(ty + i) * R + tx] = __float2half(t[tx][ty + i]);
}

// ---------------- GEMM1: H = silu(X W1) * (X W3) -----------------------------
// CTA 128m x 64n, k-chunk 64. Stage: A 16K | B-w1 8K | B-w3 8K = 32KB x2.
#define G_STAGE 32768
#define G_SMEM  (1024 + 2*G_STAGE)

__global__ __launch_bounds__(256, 2) void k_gemm1() {
    int e = blockIdx.z;
    int cnt = g_cnt[e];
    int m0 = blockIdx.x * 128;
    if (m0 >= cnt) return;
    int n0 = blockIdx.y * 64;

    extern __shared__ char smem[];
    int* rows = (int*)smem;
    uint32_t sb = s2u(smem);
    uint32_t st[2] = {sb + 1024, sb + 1024 + G_STAGE};
    int tid = threadIdx.x, lane = tid & 31, wid = tid >> 5;

    if (tid < 128) {
        int m = m0 + tid;
        rows[tid] = g_slot[e][m < cnt ? m : cnt - 1];
    }
    __syncthreads();

    const __half* w1 = g_w1 + (size_t)e * DINTER * DMODEL;
    const __half* w3 = g_w3 + (size_t)e * DINTER * DMODEL;

    auto load_stage = [&](int it) {
        uint32_t base = st[it & 1];
        int k0 = it * 64;
#pragma unroll
        for (int q = 0; q < 4; q++) {          // A: 128 rows x 8 chunks
            int i = tid + q * 256;
            int r = i >> 3, c = i & 7;
            const __half* src = g_x + (size_t)(rows[r] >> 1) * DMODEL + k0 + c * 8;
            cp16(base + SWZ(r * 128 + c * 16), src);
        }
#pragma unroll
        for (int q = 0; q < 4; q++) {          // B: 2 mats x 64 rows x 8 chunks
            int i = tid + q * 256;
            int r = i >> 3, c = i & 7;
            int blk = r >> 6, rr = r & 63;
            const __half* src = (blk ? w3 : w1) + (size_t)(n0 + rr) * DMODEL + k0 + c * 8;
            cp16(base + 16384 + blk * 8192 + SWZ(rr * 128 + c * 16), src);
        }
        CP_COMMIT();
    };

    float acc1[2][4][4] = {}, acc3[2][4][4] = {};
    int m0w = (wid & 3) * 32, n0w = (wid >> 2) * 32;

    load_stage(0);
    load_stage(1);
    const int ITERS = DMODEL / 64;   // 16
    for (int it = 0; it < ITERS; ++it) {
        if (it + 1 < ITERS) CP_WAIT1(); else CP_WAIT0();
        __syncthreads();
        uint32_t a = st[it & 1], b = st[it & 1] + 16384;
#pragma unroll
        for (int ks = 0; ks < 4; ++ks) {
            uint32_t ah[2][4];
            int colh = ks * 32 + ((lane >> 4) << 4);
#pragma unroll
            for (int i = 0; i < 2; i++) {
                int row = m0w + i * 16 + (lane & 15);
                ldsm4(ah[i][0], ah[i][1], ah[i][2], ah[i][3], a + SWZ(row * 128 + colh));
            }
            // B: ldsm4 loads j-pairs: lanes 0-15 -> j, lanes 16-31 -> j+1
            int rowb_off = (lane >> 4) * 8 + (lane & 7);
            int colb = ks * 32 + ((lane & 8) << 1);
#pragma unroll
            for (int jj = 0; jj < 2; jj++) {
                int rn = n0w + jj * 16 + rowb_off;
                uint32_t b1[4], b3[4];
                ldsm4(b1[0], b1[1], b1[2], b1[3], b + SWZ(rn * 128 + colb));
                ldsm4(b3[0], b3[1], b3[2], b3[3], b + 8192 + SWZ(rn * 128 + colb));
#pragma unroll
                for (int i = 0; i < 2; i++) {
                    mma16816(acc1[i][jj * 2 + 0], ah[i], b1 + 0);
                    mma16816(acc1[i][jj * 2 + 1], ah[i], b1 + 2);
                    mma16816(acc3[i][jj * 2 + 0], ah[i], b3 + 0);
                    mma16816(acc3[i][jj * 2 + 1], ah[i], b3 + 2);
                }
            }
        }
        __syncthreads();
        if (it + 2 < ITERS) load_stage(it + 2);
    }

    // epilogue: silu(acc1)*acc3, fp16, store H
    int gr = lane >> 2, gc = (lane & 3) * 2;
#pragma unroll
    for (int i = 0; i < 2; i++) {
#pragma unroll
        for (int half = 0; half < 2; half++) {
            int m = m0w + i * 16 + gr + half * 8;
            if (m0 + m < cnt) {
                int slot = rows[m];
                __half* ph = g_h + (size_t)slot * DINTER + n0 + n0w;
#pragma unroll
                for (int j = 0; j < 4; j++) {
                    float a0 = acc1[i][j][half * 2 + 0], a1 = acc1[i][j][half * 2 + 1];
                    float c0 = acc3[i][j][half * 2 + 0], c1 = acc3[i][j][half * 2 + 1];
                    float s0 = a0 / (1.f + __expf(-a0)) * c0;
                    float s1 = a1 / (1.f + __expf(-a1)) * c1;
                    union { __half b[2]; uint32_t u; } uh;
                    uh.b[0] = __float2half(s0);
                    uh.b[1] = __float2half(s1);
                    *(uint32_t*)(ph + j * 8 + gc) = uh.u;
                }
            }
        }
    }
}

// ---------------- GEMM2: out += gate * (H W2) --------------------------------
// CTA 128m x 128n, k-chunk 64, 11 iters. warp = 32m x 64n.
__global__ __launch_bounds__(256, 2) void k_gemm2(float* __restrict__ out) {
    int e = blockIdx.z;
    int cnt = g_cnt[e];
    int m0 = blockIdx.x * 128;
    if (m0 >= cnt) return;
    int n0 = blockIdx.y * 128;

    extern __shared__ char smem[];
    int*   rows  = (int*)smem;
    float* gates = (float*)(smem + 512);
    uint32_t sb = s2u(smem);
    uint32_t st[2] = {sb + 1024, sb + 1024 + G_STAGE};
    int tid = threadIdx.x, lane = tid & 31, wid = tid >> 5;

    if (tid < 128) {
        int m = m0 + tid;
        int mm = m < cnt ? m : cnt - 1;
        rows[tid]  = g_slot[e][mm];
        gates[tid] = g_gate[e][mm];
    }
    __syncthreads();

    const __half* w2 = g_w2 + (size_t)e * DMODEL * DINTER;

    auto load_stage = [&](int it) {
        uint32_t base = st[it & 1];
        int k0 = it * 64;
#pragma unroll
        for (int q = 0; q < 4; q++) {          // A: 128 gathered H rows
            int i = tid + q * 256;
            int r = i >> 3, c = i & 7;
            const __half* src = g_h + (size_t)rows[r] * DINTER + k0 + c * 8;
            cp16(base + SWZ(r * 128 + c * 16), src);
        }
#pragma unroll
        for (int q = 0; q < 4; q++) {          // B: 128 n-rows of W2T
            int i = tid + q * 256;
            int r = i >> 3, c = i & 7;
            const __half* src = w2 + (size_t)(n0 + r) * DINTER + k0 + c * 8;
            cp16(base + 16384 + SWZ(r * 128 + c * 16), src);
        }
        CP_COMMIT();
    };

    float acc[2][8][4] = {};
    int m0w = (wid & 3) * 32, n0w = (wid >> 2) * 64;

    load_stage(0);
    load_stage(1);
    const int ITERS = DINTER / 64;   // 11
    for (int it = 0; it < ITERS; ++it) {
        if (it + 1 < ITERS) CP_WAIT1(); else CP_WAIT0();
        __syncthreads();
        uint32_t a = st[it & 1], b = st[it & 1] + 16384;
#pragma unroll
        for (int ks = 0; ks < 4; ++ks) {
            uint32_t ah[2][4];
            int colh = ks * 32 + ((lane >> 4) << 4);
#pragma unroll
            for (int i = 0; i < 2; i++) {
                int row = m0w + i * 16 + (lane & 15);
                ldsm4(ah[i][0], ah[i][1], ah[i][2], ah[i][3], a + SWZ(row * 128 + colh));
            }
            int rowb_off = (lane >> 4) * 8 + (lane & 7);
            int colb = ks * 32 + ((lane & 8) << 1);
#pragma unroll
            for (int jj = 0; jj < 4; jj++) {
                int rn = n0w + jj * 16 + rowb_off;
                uint32_t bw[4];
                ldsm4(bw[0], bw[1], bw[2], bw[3], b + SWZ(rn * 128 + colb));
#pragma unroll
                for (int i = 0; i < 2; i++) {
                    mma16816(acc[i][jj * 2 + 0], ah[i], bw + 0);
                    mma16816(acc[i][jj * 2 + 1], ah[i], bw + 2);
                }
            }
        }
        __syncthreads();
        if (it + 2 < ITERS) load_stage(it + 2);
    }

    int gr = lane >> 2, gc = (lane & 3) * 2;
#pragma unroll
    for (int i = 0; i < 2; i++) {
#pragma unroll
        for (int half = 0; half < 2; half++) {
            int m = m0w + i * 16 + gr + half * 8;
            if (m0 + m < cnt) {
                int tok = rows[m] >> 1;
                float g = gates[m];
                float* op = out + (size_t)tok * DMODEL + n0 + n0w;
#pragma unroll
                for (int j = 0; j < 8; j++) {
                    atomicAdd(op + j * 8 + gc + 0, g * acc[i][j][half * 2 + 0]);
                    atomicAdd(op + j * 8 + gc + 1, g * acc[i][j][half * 2 + 1]);
                }
            }
        }
    }
}

// ---------------------------------------------------------------------------
extern "C" void kernel_launch(void* const* d_in, const int* in_sizes, int n_in,
                              void* d_out, int out_size) {
    const float* x  = (const float*)d_in[0];
    const float* Wg = (const float*)d_in[1];
    const float* W1 = (const float*)d_in[2];
    const float* W2 = (const float*)d_in[3];
    const float* W3 = (const float*)d_in[4];
    float* out = (float*)d_out;

    cudaFuncSetAttribute(k_gemm1, cudaFuncAttributeMaxDynamicSharedMemorySize, G_SMEM);
    cudaFuncSetAttribute(k_gemm2, cudaFuncAttributeMaxDynamicSharedMemorySize, G_SMEM);

    cudaMemsetAsync(d_out, 0, (size_t)out_size * sizeof(float), 0);
    k_reset<<<1, 32>>>();
    k_router<<<NTOK, 128>>>(x, Wg);
    k_cvt_x<<<(NTOK * DMODEL / 4) / 256, 256>>>(x);
    dim3 tb(32, 8);
    k_cvtT<<<dim3(DMODEL / 32, DINTER / 32, NEXP), tb>>>(W1, 0, DMODEL, DINTER);
    k_cvtT<<<dim3(DMODEL / 32, DINTER / 32, NEXP), tb>>>(W3, 1, DMODEL, DINTER);
    k_cvtT<<<dim3(DINTER / 32, DMODEL / 32, NEXP), tb>>>(W2, 2, DINTER, DMODEL);

    k_gemm1<<<dim3(NTOK / 128, DINTER / 64, NEXP), 256, G_SMEM>>>();
    k_gemm2<<<dim3(NTOK / 128, DMODEL / 128, NEXP), 256, G_SMEM>>>(out);
}

// round 12
// speedup vs baseline: 4.4990x; 1.0671x over previous
#include <cuda_runtime.h>
#include <cuda_fp16.h>
#include <math.h>
#include <stdint.h>

#define NTOK   4096
#define DMODEL 1024
#define DINTER 704
#define NEXP   16
#define NSLOT  (NTOK*2)

// ---------------- device scratch (no allocations allowed) -------------------
__device__ int   g_cnt[NEXP];
__device__ int   g_slot[NEXP][NTOK];
__device__ float g_gate[NEXP][NTOK];

__device__ __align__(16) __half g_x[(size_t)NTOK*DMODEL];
// weights in NATIVE [k][n] layout, fp16: W1/W3 [e][1024][704], W2 [e][704][1024]
__device__ __align__(16) __half g_w1[(size_t)NEXP*DMODEL*DINTER];
__device__ __align__(16) __half g_w3[(size_t)NEXP*DMODEL*DINTER];
__device__ __align__(16) __half g_w2[(size_t)NEXP*DINTER*DMODEL];
__device__ __align__(16) __half g_h[(size_t)NSLOT*DINTER];

// ---------------- PTX helpers ----------------------------------------------
__device__ __forceinline__ uint32_t s2u(const void* p) {
    uint32_t a;
    asm("{ .reg .u64 t; cvta.to.shared.u64 t, %1; cvt.u32.u64 %0, t; }" : "=r"(a) : "l"(p));
    return a;
}
#define SWZ(o) ((o) ^ (((o) >> 3) & 0x70))

__device__ __forceinline__ void cp16(uint32_t dst, const void* src) {
    asm volatile("cp.async.cg.shared.global [%0], [%1], 16;" :: "r"(dst), "l"(src));
}
#define CP_COMMIT() asm volatile("cp.async.commit_group;" ::: "memory")
#define CP_WAIT1()  asm volatile("cp.async.wait_group 1;" ::: "memory")
#define CP_WAIT0()  asm volatile("cp.async.wait_group 0;" ::: "memory")

__device__ __forceinline__ void ldsm4(uint32_t& r0, uint32_t& r1, uint32_t& r2, uint32_t& r3,
                                      uint32_t addr) {
    asm volatile("ldmatrix.sync.aligned.m8n8.x4.shared.b16 {%0,%1,%2,%3}, [%4];"
                 : "=r"(r0), "=r"(r1), "=r"(r2), "=r"(r3) : "r"(addr));
}
__device__ __forceinline__ void ldsm4t(uint32_t& r0, uint32_t& r1, uint32_t& r2, uint32_t& r3,
                                       uint32_t addr) {
    asm volatile("ldmatrix.sync.aligned.m8n8.x4.trans.shared.b16 {%0,%1,%2,%3}, [%4];"
                 : "=r"(r0), "=r"(r1), "=r"(r2), "=r"(r3) : "r"(addr));
}
__device__ __forceinline__ void mma16816(float* d, const uint32_t* a, const uint32_t* b) {
    asm volatile(
        "mma.sync.aligned.m16n8k16.row.col.f32.f16.f16.f32 "
        "{%0,%1,%2,%3},{%4,%5,%6,%7},{%8,%9},{%0,%1,%2,%3};"
        : "+f"(d[0]), "+f"(d[1]), "+f"(d[2]), "+f"(d[3])
        : "r"(a[0]), "r"(a[1]), "r"(a[2]), "r"(a[3]), "r"(b[0]), "r"(b[1]));
}

// ---------------- small kernels ----------------------------------------------
__global__ void k_reset() {
    if (threadIdx.x < NEXP) g_cnt[threadIdx.x] = 0;
}

__global__ void k_router(const float* __restrict__ x, const float* __restrict__ Wg) {
    int n = blockIdx.x;
    const float* xr = x + (size_t)n * DMODEL;
    int tid = threadIdx.x;
    int e = tid >> 3, l = tid & 7;
    const float* wr = Wg + e * DMODEL;
    float s = 0.f;
#pragma unroll 8
    for (int d = l; d < DMODEL; d += 8) s += xr[d] * wr[d];
    s += __shfl_down_sync(0xffffffffu, s, 4);
    s += __shfl_down_sync(0xffffffffu, s, 2);
    s += __shfl_down_sync(0xffffffffu, s, 1);
    __shared__ float logits[NEXP];
    if (l == 0) logits[e] = s;
    __syncthreads();
    if (tid == 0) {
        int i1 = 0; float v1 = logits[0];
#pragma unroll
        for (int j = 1; j < NEXP; j++) if (logits[j] > v1) { v1 = logits[j]; i1 = j; }
        int i2 = -1; float v2 = -3.4e38f;
#pragma unroll
        for (int j = 0; j < NEXP; j++) if (j != i1 && logits[j] > v2) { v2 = logits[j]; i2 = j; }
        float w1 = 1.f / (1.f + expf(v2 - v1));
        float w2 = 1.f - w1;
        int p1 = atomicAdd(&g_cnt[i1], 1);
        g_slot[i1][p1] = n * 2;     g_gate[i1][p1] = w1;
        int p2 = atomicAdd(&g_cnt[i2], 1);
        g_slot[i2][p2] = n * 2 + 1; g_gate[i2][p2] = w2;
    }
}

// fused streaming fp32 -> fp16 conversion: W1 | W3 | W2 | x, 8 elems/thread
#define WGRP ((size_t)NEXP*DMODEL*DINTER/8)   // 1441792
#define XGRP ((size_t)NTOK*DMODEL/8)          // 524288
__global__ void k_cvt_all(const float* __restrict__ x,  const float* __restrict__ W1,
                          const float* __restrict__ W3, const float* __restrict__ W2) {
    size_t gid = (size_t)blockIdx.x * blockDim.x + threadIdx.x;
    const float* src; __half* dst; size_t off;
    if (gid < WGRP)            { src = W1; dst = g_w1; off = gid; }
    else if (gid < 2 * WGRP)   { src = W3; dst = g_w3; off = gid - WGRP; }
    else if (gid < 3 * WGRP)   { src = W2; dst = g_w2; off = gid - 2 * WGRP; }
    else                       { src = x;  dst = g_x;  off = gid - 3 * WGRP;
                                 if (off >= XGRP) return; }
    float4 v0 = ((const float4*)src)[off * 2];
    float4 v1 = ((const float4*)src)[off * 2 + 1];
    __half h[8] = {__float2half(v0.x), __float2half(v0.y), __float2half(v0.z), __float2half(v0.w),
                   __float2half(v1.x), __float2half(v1.y), __float2half(v1.z), __float2half(v1.w)};
    ((uint4*)dst)[off] = *(uint4*)h;
}

// ---------------- GEMM1: H = silu(X W1) * (X W3) -----------------------------
// CTA 128m x 64n, k-chunk 64, 3-stage single-sync pipeline.
// Stage: A 16KB (SW128, 128B rows) | B 2 mats x 64 k-rows x 144B (padded) = 34816B
#define G1_BROW  144
#define G1_STAGE (16384 + 2*64*G1_BROW)
#define G1_SMEM  (1024 + 3*G1_STAGE)

__global__ __launch_bounds__(256, 2) void k_gemm1() {
    int e = blockIdx.z;
    int cnt = g_cnt[e];
    int m0 = blockIdx.x * 128;
    if (m0 >= cnt) return;
    int n0 = blockIdx.y * 64;

    extern __shared__ char smem[];
    int* rows = (int*)smem;
    uint32_t sb = s2u(smem);
    int tid = threadIdx.x, lane = tid & 31, wid = tid >> 5;

    if (tid < 128) {
        int m = m0 + tid;
        rows[tid] = g_slot[e][m < cnt ? m : cnt - 1];
    }
    __syncthreads();

    const __half* w1 = g_w1 + (size_t)e * DMODEL * DINTER;
    const __half* w3 = g_w3 + (size_t)e * DMODEL * DINTER;

    auto load_stage = [&](int it) {
        uint32_t base = sb + 1024 + (it % 3) * G1_STAGE;
        int k0 = it * 64;
#pragma unroll
        for (int q = 0; q < 4; q++) {          // A: 128 rows x 8 chunks, SW128
            int i = tid + q * 256;
            int r = i >> 3, c = i & 7;
            const __half* src = g_x + (size_t)(rows[r] >> 1) * DMODEL + k0 + c * 8;
            cp16(base + SWZ(r * 128 + c * 16), src);
        }
#pragma unroll
        for (int q = 0; q < 4; q++) {          // B: 2 mats x 64 k-rows x 8 chunks, [k][n]
            int i = tid + q * 256;
            int c = i & 7;
            int r = (i >> 3) & 63;
            int mat = i >> 9;
            const __half* src = (mat ? w3 : w1) + (size_t)(k0 + r) * DINTER + n0 + c * 8;
            cp16(base + 16384 + mat * (64 * G1_BROW) + r * G1_BROW + c * 16, src);
        }
        CP_COMMIT();
    };

    float acc1[2][4][4] = {}, acc3[2][4][4] = {};
    int m0w = (wid & 3) * 32, n0w = (wid >> 2) * 32;

    load_stage(0);
    load_stage(1);
    const int ITERS = DMODEL / 64;   // 16
    for (int it = 0; it < ITERS; ++it) {
        if (it + 1 < ITERS) CP_WAIT1(); else CP_WAIT0();
        __syncthreads();
        if (it + 2 < ITERS) load_stage(it + 2);
        uint32_t a = sb + 1024 + (it % 3) * G1_STAGE;
        uint32_t b = a + 16384;
#pragma unroll
        for (int ks = 0; ks < 4; ++ks) {
            uint32_t ah[2][4];
            int colh = ks * 32 + ((lane >> 4) << 4);
#pragma unroll
            for (int i = 0; i < 2; i++) {
                int row = m0w + i * 16 + (lane & 15);
                ldsm4(ah[i][0], ah[i][1], ah[i][2], ah[i][3], a + SWZ(row * 128 + colh));
            }
            // trans B: lane -> k-row = ks*16 + ((lane>>3)&1)*8 + (lane&7),
            //          n-col base  = jj*16 + (lane>>4)*8
            int kl = ks * 16 + ((lane >> 3) & 1) * 8 + (lane & 7);
            int nb = (lane >> 4) * 8;
#pragma unroll
            for (int jj = 0; jj < 2; jj++) {
                int nc = n0w + jj * 16 + nb;
                uint32_t b1[4], b3[4];
                ldsm4t(b1[0], b1[1], b1[2], b1[3], b + kl * G1_BROW + nc * 2);
                ldsm4t(b3[0], b3[1], b3[2], b3[3], b + 64 * G1_BROW + kl * G1_BROW + nc * 2);
#pragma unroll
                for (int i = 0; i < 2; i++) {
                    mma16816(acc1[i][jj * 2 + 0], ah[i], b1 + 0);
                    mma16816(acc1[i][jj * 2 + 1], ah[i], b1 + 2);
                    mma16816(acc3[i][jj * 2 + 0], ah[i], b3 + 0);
                    mma16816(acc3[i][jj * 2 + 1], ah[i], b3 + 2);
                }
            }
        }
    }

    // epilogue: silu(acc1)*acc3, fp16, store H
    int gr = lane >> 2, gc = (lane & 3) * 2;
#pragma unroll
    for (int i = 0; i < 2; i++) {
#pragma unroll
        for (int half = 0; half < 2; half++) {
            int m = m0w + i * 16 + gr + half * 8;
            if (m0 + m < cnt) {
                int slot = rows[m];
                __half* ph = g_h + (size_t)slot * DINTER + n0 + n0w;
#pragma unroll
                for (int j = 0; j < 4; j++) {
                    float a0 = acc1[i][j][half * 2 + 0], a1 = acc1[i][j][half * 2 + 1];
                    float c0 = acc3[i][j][half * 2 + 0], c1 = acc3[i][j][half * 2 + 1];
                    float s0 = a0 / (1.f + __expf(-a0)) * c0;
                    float s1 = a1 / (1.f + __expf(-a1)) * c1;
                    union { __half b[2]; uint32_t u; } uh;
                    uh.b[0] = __float2half(s0);
                    uh.b[1] = __float2half(s1);
                    *(uint32_t*)(ph + j * 8 + gc) = uh.u;
                }
            }
        }
    }
}

// ---------------- GEMM2: out += gate * (H W2) --------------------------------
// CTA 128m x 128n, k-chunk 64, 11 iters, 3-stage. warp = 32m x 64n.
// Stage: A 16KB | B 64 k-rows x 272B (padded) = 33792B
#define G2_BROW  272
#define G2_STAGE (16384 + 64*G2_BROW)
#define G2_SMEM  (1024 + 3*G2_STAGE)

__global__ __launch_bounds__(256, 2) void k_gemm2(float* __restrict__ out) {
    int e = blockIdx.z;
    int cnt = g_cnt[e];
    int m0 = blockIdx.x * 128;
    if (m0 >= cnt) return;
    int n0 = blockIdx.y * 128;

    extern __shared__ char smem[];
    int*   rows  = (int*)smem;
    float* gates = (float*)(smem + 512);
    uint32_t sb = s2u(smem);
    int tid = threadIdx.x, lane = tid & 31, wid = tid >> 5;

    if (tid < 128) {
        int m = m0 + tid;
        int mm = m < cnt ? m : cnt - 1;
        rows[tid]  = g_slot[e][mm];
        gates[tid] = g_gate[e][mm];
    }
    __syncthreads();

    const __half* w2 = g_w2 + (size_t)e * DINTER * DMODEL;

    auto load_stage = [&](int it) {
        uint32_t base = sb + 1024 + (it % 3) * G2_STAGE;
        int k0 = it * 64;
#pragma unroll
        for (int q = 0; q < 4; q++) {          // A: 128 gathered H rows, SW128
            int i = tid + q * 256;
            int r = i >> 3, c = i & 7;
            const __half* src = g_h + (size_t)rows[r] * DINTER + k0 + c * 8;
            cp16(base + SWZ(r * 128 + c * 16), src);
        }
#pragma unroll
        for (int q = 0; q < 4; q++) {          // B: 64 k-rows x 16 chunks (128 n), [k][n]
            int i = tid + q * 256;
            int c = i & 15;
            int r = i >> 4;
            const __half* src = w2 + (size_t)(k0 + r) * DMODEL + n0 + c * 8;
            cp16(base + 16384 + r * G2_BROW + c * 16, src);
        }
        CP_COMMIT();
    };

    float acc[2][8][4] = {};
    int m0w = (wid & 3) * 32, n0w = (wid >> 2) * 64;

    load_stage(0);
    load_stage(1);
    const int ITERS = DINTER / 64;   // 11
    for (int it = 0; it < ITERS; ++it) {
        if (it + 1 < ITERS) CP_WAIT1(); else CP_WAIT0();
        __syncthreads();
        if (it + 2 < ITERS) load_stage(it + 2);
        uint32_t a = sb + 1024 + (it % 3) * G2_STAGE;
        uint32_t b = a + 16384;
#pragma unroll
        for (int ks = 0; ks < 4; ++ks) {
            uint32_t ah[2][4];
            int colh = ks * 32 + ((lane >> 4) << 4);
#pragma unroll
            for (int i = 0; i < 2; i++) {
                int row = m0w + i * 16 + (lane & 15);
                ldsm4(ah[i][0], ah[i][1], ah[i][2], ah[i][3], a + SWZ(row * 128 + colh));
            }
            int kl = ks * 16 + ((lane >> 3) & 1) * 8 + (lane & 7);
            int nb = (lane >> 4) * 8;
#pragma unroll
            for (int jj = 0; jj < 4; jj++) {
                int nc = n0w + jj * 16 + nb;
                uint32_t bw[4];
                ldsm4t(bw[0], bw[1], bw[2], bw[3], b + kl * G2_BROW + nc * 2);
#pragma unroll
                for (int i = 0; i < 2; i++) {
                    mma16816(acc[i][jj * 2 + 0], ah[i], bw + 0);
                    mma16816(acc[i][jj * 2 + 1], ah[i], bw + 2);
                }
            }
        }
    }

    int gr = lane >> 2, gc = (lane & 3) * 2;
#pragma unroll
    for (int i = 0; i < 2; i++) {
#pragma unroll
        for (int half = 0; half < 2; half++) {
            int m = m0w + i * 16 + gr + half * 8;
            if (m0 + m < cnt) {
                int tok = rows[m] >> 1;
                float g = gates[m];
                float* op = out + (size_t)tok * DMODEL + n0 + n0w;
#pragma unroll
                for (int j = 0; j < 8; j++) {
                    atomicAdd(op + j * 8 + gc + 0, g * acc[i][j][half * 2 + 0]);
                    atomicAdd(op + j * 8 + gc + 1, g * acc[i][j][half * 2 + 1]);
                }
            }
        }
    }
}

// ---------------------------------------------------------------------------
extern "C" void kernel_launch(void* const* d_in, const int* in_sizes, int n_in,
                              void* d_out, int out_size) {
    const float* x  = (const float*)d_in[0];
    const float* Wg = (const float*)d_in[1];
    const float* W1 = (const float*)d_in[2];
    const float* W2 = (const float*)d_in[3];
    const float* W3 = (const float*)d_in[4];
    float* out = (float*)d_out;

    cudaFuncSetAttribute(k_gemm1, cudaFuncAttributeMaxDynamicSharedMemorySize, G1_SMEM);
    cudaFuncSetAttribute(k_gemm2, cudaFuncAttributeMaxDynamicSharedMemorySize, G2_SMEM);

    cudaMemsetAsync(d_out, 0, (size_t)out_size * sizeof(float), 0);
    k_reset<<<1, 32>>>();
    k_router<<<NTOK, 128>>>(x, Wg);
    int cvt_blocks = (int)((3 * WGRP + XGRP + 255) / 256);
    k_cvt_all<<<cvt_blocks, 256>>>(x, W1, W3, W2);

    k_gemm1<<<dim3(NTOK / 128, DINTER / 64, NEXP), 256, G1_SMEM>>>();
    k_gemm2<<<dim3(NTOK / 128, DMODEL / 128, NEXP), 256, G2_SMEM>>>(out);
}